// round 13
// baseline (speedup 1.0000x reference)
#include <cuda_runtime.h>
#include <cuda_bf16.h>
#include <stdint.h>
#include <math.h>

#define BATCH 4
#define SEQ   1024
#define EMB   1024
#define HEADS 16
#define HDIM  64
#define HID   1024
#define WIN   128
#define NREL  257
#define NRELP 272
#define SCALE 0.03125f

// ---------------- scratch ----------------
__device__ float g_qc[(size_t)BATCH*HEADS*SEQ*HDIM];   // [bh][t][d] tf32
__device__ float g_qr[(size_t)BATCH*HEADS*SEQ*HDIM];   // [bh][t][d] tf32
__device__ float g_k [(size_t)BATCH*HEADS*SEQ*HDIM];   // [bh][t][d] tf32
__device__ float g_v [(size_t)BATCH*HEADS*SEQ*HDIM];   // [bh][d][t] tf32 (transposed)
__device__ float g_ao[(size_t)BATCH*SEQ*HID];          // [b][t][hid] tf32
__device__ float g_rwin[NRELP*64];                     // [u][d] tf32
// pre-rounded tf32 copies of GEMM inputs
__device__ float g_xr[(size_t)BATCH*SEQ*EMB];
__device__ float g_wq[(size_t)EMB*HID];
__device__ float g_wk[(size_t)EMB*HID];
__device__ float g_wv[(size_t)EMB*HID];
__device__ float g_wo[(size_t)HID*EMB];

__device__ __forceinline__ float to_tf32(float x) {
    unsigned int r;
    asm("cvt.rna.tf32.f32 %0, %1;" : "=r"(r) : "f"(x));
    return __uint_as_float(r);
}
__device__ __forceinline__ float4 rnd4(float4 v) {
    v.x = to_tf32(v.x); v.y = to_tf32(v.y);
    v.z = to_tf32(v.z); v.w = to_tf32(v.w);
    return v;
}

// cp.async helpers (smem dst MUST be 16B aligned)
__device__ __forceinline__ void cp16(unsigned int dst_smem, const void* src) {
    asm volatile("cp.async.ca.shared.global [%0], [%1], 16;" :: "r"(dst_smem), "l"(src));
}
__device__ __forceinline__ void cp_commit() { asm volatile("cp.async.commit_group;"); }
__device__ __forceinline__ void cp_wait0()  { asm volatile("cp.async.wait_group 0;" ::: "memory"); }

// ---------------- prep: round inputs to tf32 once ----------------
#define XN4 ((BATCH*SEQ*EMB)/4)
#define WN4 ((EMB*HID)/4)
__global__ void prep_round(const float* __restrict__ X,
                           const float* __restrict__ Wq, const float* __restrict__ Wk,
                           const float* __restrict__ Wv, const float* __restrict__ Wo,
                           float* __restrict__ xr, float* __restrict__ wq,
                           float* __restrict__ wk, float* __restrict__ wv,
                           float* __restrict__ wo) {
    int idx = blockIdx.x * blockDim.x + threadIdx.x;
    if (idx < XN4) {
        ((float4*)xr)[idx] = rnd4(((const float4*)X)[idx]);
    } else if (idx < XN4 + WN4) {
        int i = idx - XN4;      ((float4*)wq)[i] = rnd4(((const float4*)Wq)[i]);
    } else if (idx < XN4 + 2*WN4) {
        int i = idx - XN4 - WN4; ((float4*)wk)[i] = rnd4(((const float4*)Wk)[i]);
    } else if (idx < XN4 + 3*WN4) {
        int i = idx - XN4 - 2*WN4; ((float4*)wv)[i] = rnd4(((const float4*)Wv)[i]);
    } else if (idx < XN4 + 4*WN4) {
        int i = idx - XN4 - 3*WN4; ((float4*)wo)[i] = rnd4(((const float4*)Wo)[i]);
    }
}

// ---------------- Rwin precompute ----------------
__global__ void rwin_kernel(const float* __restrict__ W_rel,
                            const float* __restrict__ b_rel,
                            float* __restrict__ Rwin) {
    int gid = blockIdx.x * blockDim.x + threadIdx.x;
    if (gid >= NRELP * 64) return;
    int d = gid & 63;
    int u = gid >> 6;
    float out = 0.0f;
    if (u < NREL) {
        float pos = (float)(u - WIN);
        float s = b_rel[d];
        #pragma unroll 8
        for (int f = 0; f < 32; f++) {
            float inv = powf(10000.0f, -(2.0f * (float)f) / 64.0f);
            float a = pos * inv;
            s += sinf(a) * W_rel[f * 64 + d];
            s += cosf(a) * W_rel[(f + 32) * 64 + d];
        }
        out = to_tf32(s);
    }
    Rwin[u * 64 + d] = out;
}

// ---------------- mma primitive ----------------
__device__ __forceinline__ void mma8(float c[4], float2 alo, float2 ahi, float b0, float b1) {
    asm volatile(
        "mma.sync.aligned.m16n8k8.row.col.f32.tf32.tf32.f32 "
        "{%0,%1,%2,%3}, {%4,%5,%6,%7}, {%8,%9}, {%0,%1,%2,%3};"
        : "+f"(c[0]), "+f"(c[1]), "+f"(c[2]), "+f"(c[3])
        : "r"(__float_as_uint(alo.x)), "r"(__float_as_uint(ahi.x)),
          "r"(__float_as_uint(alo.y)), "r"(__float_as_uint(ahi.y)),
          "r"(__float_as_uint(b0)),   "r"(__float_as_uint(b1)));
}

#define ASTR 20     // 80 bytes/row: 16B-aligned for cp.async at every (am, ak)
#define BS2  18     // Bs [n=128][k=16] stride

// ============ GEMM: 128x128 block, 4 warps, 64x64 warp tiles ============
// A via cp.async (pre-rounded tf32 global). B via LDG + transpose-scatter STS
// into [n][k] layout so B-fragments are a single LDS.64.

// ---------------- fused QKV GEMM ----------------
__global__ void __launch_bounds__(128, 2)
gemm_qkv_tf32(const float* __restrict__ X,
              const float* __restrict__ Wq, const float* __restrict__ Wk,
              const float* __restrict__ Wv,
              const float* __restrict__ cb, const float* __restrict__ rb,
              float* __restrict__ qc, float* __restrict__ qr,
              float* __restrict__ kt, float* __restrict__ vt) {
    __shared__ float As[2][128 * ASTR];
    __shared__ float Bs[2][128 * BS2];

    int tid = threadIdx.x;
    int wid = tid >> 5, lane = tid & 31;
    int lr = lane >> 2, lq = lane & 3;
    int wm = wid & 1, wn = wid >> 1;
    int which = blockIdx.x >> 3;
    const float* B = (which == 0) ? Wq : ((which == 1) ? Wk : Wv);
    int n0 = (blockIdx.x & 7) * 128;
    int m0 = blockIdx.y * 128;

    int am[4], ak[4], bk[4], bn[4];
    unsigned int adst[2][4];
    #pragma unroll
    for (int l = 0; l < 4; l++) {
        int fidx = tid + 128 * l;
        am[l] = fidx >> 2;  ak[l] = (fidx & 3) << 2;
        bk[l] = fidx >> 5;  bn[l] = (fidx & 31) << 2;
        adst[0][l] = (unsigned int)__cvta_generic_to_shared(&As[0][am[l] * ASTR + ak[l]]);
        adst[1][l] = (unsigned int)__cvta_generic_to_shared(&As[1][am[l] * ASTR + ak[l]]);
    }

    float acc[4][8][4];
    #pragma unroll
    for (int mt = 0; mt < 4; mt++)
        #pragma unroll
        for (int nt = 0; nt < 8; nt++)
            #pragma unroll
            for (int r = 0; r < 4; r++) acc[mt][nt][r] = 0.0f;

    float4 pb[4];
    // preload tile 0
    #pragma unroll
    for (int l = 0; l < 4; l++) {
        pb[l] = *(const float4*)(B + (size_t)bk[l] * HID + n0 + bn[l]);
        cp16(adst[0][l], X + (size_t)(m0 + am[l]) * EMB + ak[l]);
    }
    cp_commit();
    #pragma unroll
    for (int l = 0; l < 4; l++) {
        float* p = &Bs[0][0];
        p[(bn[l] + 0) * BS2 + bk[l]] = pb[l].x;
        p[(bn[l] + 1) * BS2 + bk[l]] = pb[l].y;
        p[(bn[l] + 2) * BS2 + bk[l]] = pb[l].z;
        p[(bn[l] + 3) * BS2 + bk[l]] = pb[l].w;
    }
    cp_wait0();
    __syncthreads();

    for (int ks = 0; ks < 64; ks++) {
        int cur = ks & 1;
        if (ks < 63) {
            int k0 = (ks + 1) * 16;
            #pragma unroll
            for (int l = 0; l < 4; l++) {
                pb[l] = *(const float4*)(B + (size_t)(k0 + bk[l]) * HID + n0 + bn[l]);
                cp16(adst[cur ^ 1][l], X + (size_t)(m0 + am[l]) * EMB + k0 + ak[l]);
            }
            cp_commit();
        }
        #pragma unroll
        for (int k8 = 0; k8 < 2; k8++) {
            int kb = k8 * 8 + 2 * lq;
            float2 av[4][2];
            #pragma unroll
            for (int mt = 0; mt < 4; mt++) {
                int r = wm * 64 + mt * 16 + lr;
                av[mt][0] = *(const float2*)&As[cur][r * ASTR + kb];
                av[mt][1] = *(const float2*)&As[cur][(r + 8) * ASTR + kb];
            }
            #pragma unroll
            for (int nt = 0; nt < 8; nt++) {
                int cc = wn * 64 + nt * 8 + lr;
                float2 bv = *(const float2*)&Bs[cur][cc * BS2 + kb];
                #pragma unroll
                for (int mt = 0; mt < 4; mt++)
                    mma8(acc[mt][nt], av[mt][0], av[mt][1], bv.x, bv.y);
            }
        }
        if (ks < 63) {
            float* p = &Bs[cur ^ 1][0];
            #pragma unroll
            for (int l = 0; l < 4; l++) {
                p[(bn[l] + 0) * BS2 + bk[l]] = pb[l].x;
                p[(bn[l] + 1) * BS2 + bk[l]] = pb[l].y;
                p[(bn[l] + 2) * BS2 + bk[l]] = pb[l].z;
                p[(bn[l] + 3) * BS2 + bk[l]] = pb[l].w;
            }
            cp_wait0();
        }
        __syncthreads();
    }

    #pragma unroll
    for (int mt = 0; mt < 4; mt++) {
        #pragma unroll
        for (int nt = 0; nt < 8; nt++) {
            int row = m0 + wm * 64 + mt * 16 + lr;
            int col = n0 + wn * 64 + nt * 8 + 2 * lq;
            float c0 = acc[mt][nt][0], c1 = acc[mt][nt][1];
            float c2 = acc[mt][nt][2], c3 = acc[mt][nt][3];
            int b = row >> 10, t = row & 1023;
            int hh = col >> 6, dd = col & 63;
            size_t base = (((size_t)(b * HEADS + hh)) << 16);
            if (which == 0) {
                float2 cbv = *(const float2*)&cb[col];
                float2 rbv = *(const float2*)&rb[col];
                *(float2*)&qc[base + (size_t)t * 64 + dd] =
                    make_float2(to_tf32(c0 + cbv.x), to_tf32(c1 + cbv.y));
                *(float2*)&qc[base + (size_t)(t + 8) * 64 + dd] =
                    make_float2(to_tf32(c2 + cbv.x), to_tf32(c3 + cbv.y));
                *(float2*)&qr[base + (size_t)t * 64 + dd] =
                    make_float2(to_tf32(c0 + rbv.x), to_tf32(c1 + rbv.y));
                *(float2*)&qr[base + (size_t)(t + 8) * 64 + dd] =
                    make_float2(to_tf32(c2 + rbv.x), to_tf32(c3 + rbv.y));
            } else if (which == 1) {
                *(float2*)&kt[base + (size_t)t * 64 + dd] =
                    make_float2(to_tf32(c0), to_tf32(c1));
                *(float2*)&kt[base + (size_t)(t + 8) * 64 + dd] =
                    make_float2(to_tf32(c2), to_tf32(c3));
            } else {
                vt[base + (size_t)dd * 1024 + t]           = to_tf32(c0);
                vt[base + (size_t)(dd + 1) * 1024 + t]     = to_tf32(c1);
                vt[base + (size_t)dd * 1024 + t + 8]       = to_tf32(c2);
                vt[base + (size_t)(dd + 1) * 1024 + t + 8] = to_tf32(c3);
            }
        }
    }
}

// ---------------- out-proj GEMM ----------------
__global__ void __launch_bounds__(128, 2)
gemm_proj_tf32(const float* __restrict__ A, const float* __restrict__ B,
               const float* __restrict__ bias, float* __restrict__ C) {
    __shared__ float As[2][128 * ASTR];
    __shared__ float Bs[2][128 * BS2];

    int tid = threadIdx.x;
    int wid = tid >> 5, lane = tid & 31;
    int lr = lane >> 2, lq = lane & 3;
    int wm = wid & 1, wn = wid >> 1;
    int n0 = blockIdx.x * 128, m0 = blockIdx.y * 128;

    int am[4], ak[4], bk[4], bn[4];
    unsigned int adst[2][4];
    #pragma unroll
    for (int l = 0; l < 4; l++) {
        int fidx = tid + 128 * l;
        am[l] = fidx >> 2;  ak[l] = (fidx & 3) << 2;
        bk[l] = fidx >> 5;  bn[l] = (fidx & 31) << 2;
        adst[0][l] = (unsigned int)__cvta_generic_to_shared(&As[0][am[l] * ASTR + ak[l]]);
        adst[1][l] = (unsigned int)__cvta_generic_to_shared(&As[1][am[l] * ASTR + ak[l]]);
    }

    float acc[4][8][4];
    #pragma unroll
    for (int mt = 0; mt < 4; mt++)
        #pragma unroll
        for (int nt = 0; nt < 8; nt++)
            #pragma unroll
            for (int r = 0; r < 4; r++) acc[mt][nt][r] = 0.0f;

    float4 pb[4];
    #pragma unroll
    for (int l = 0; l < 4; l++) {
        pb[l] = *(const float4*)(B + (size_t)bk[l] * EMB + n0 + bn[l]);
        cp16(adst[0][l], A + (size_t)(m0 + am[l]) * HID + ak[l]);
    }
    cp_commit();
    #pragma unroll
    for (int l = 0; l < 4; l++) {
        float* p = &Bs[0][0];
        p[(bn[l] + 0) * BS2 + bk[l]] = pb[l].x;
        p[(bn[l] + 1) * BS2 + bk[l]] = pb[l].y;
        p[(bn[l] + 2) * BS2 + bk[l]] = pb[l].z;
        p[(bn[l] + 3) * BS2 + bk[l]] = pb[l].w;
    }
    cp_wait0();
    __syncthreads();

    for (int ks = 0; ks < 64; ks++) {
        int cur = ks & 1;
        if (ks < 63) {
            int k0 = (ks + 1) * 16;
            #pragma unroll
            for (int l = 0; l < 4; l++) {
                pb[l] = *(const float4*)(B + (size_t)(k0 + bk[l]) * EMB + n0 + bn[l]);
                cp16(adst[cur ^ 1][l], A + (size_t)(m0 + am[l]) * HID + k0 + ak[l]);
            }
            cp_commit();
        }
        #pragma unroll
        for (int k8 = 0; k8 < 2; k8++) {
            int kb = k8 * 8 + 2 * lq;
            float2 av[4][2];
            #pragma unroll
            for (int mt = 0; mt < 4; mt++) {
                int r = wm * 64 + mt * 16 + lr;
                av[mt][0] = *(const float2*)&As[cur][r * ASTR + kb];
                av[mt][1] = *(const float2*)&As[cur][(r + 8) * ASTR + kb];
            }
            #pragma unroll
            for (int nt = 0; nt < 8; nt++) {
                int cc = wn * 64 + nt * 8 + lr;
                float2 bv = *(const float2*)&Bs[cur][cc * BS2 + kb];
                #pragma unroll
                for (int mt = 0; mt < 4; mt++)
                    mma8(acc[mt][nt], av[mt][0], av[mt][1], bv.x, bv.y);
            }
        }
        if (ks < 63) {
            float* p = &Bs[cur ^ 1][0];
            #pragma unroll
            for (int l = 0; l < 4; l++) {
                p[(bn[l] + 0) * BS2 + bk[l]] = pb[l].x;
                p[(bn[l] + 1) * BS2 + bk[l]] = pb[l].y;
                p[(bn[l] + 2) * BS2 + bk[l]] = pb[l].z;
                p[(bn[l] + 3) * BS2 + bk[l]] = pb[l].w;
            }
            cp_wait0();
        }
        __syncthreads();
    }

    #pragma unroll
    for (int mt = 0; mt < 4; mt++) {
        #pragma unroll
        for (int nt = 0; nt < 8; nt++) {
            int row = m0 + wm * 64 + mt * 16 + lr;
            int col = n0 + wn * 64 + nt * 8 + 2 * lq;
            float2 bb = *(const float2*)&bias[col];
            *(float2*)&C[(size_t)row * EMB + col] =
                make_float2(acc[mt][nt][0] + bb.x, acc[mt][nt][1] + bb.y);
            *(float2*)&C[(size_t)(row + 8) * EMB + col] =
                make_float2(acc[mt][nt][2] + bb.x, acc[mt][nt][3] + bb.y);
        }
    }
}

// ---------------- windowed attention (unchanged from R10) ------------------
#define TQ    64
#define AQP   68
#define RWP   68
#define PPW   272
#define KVP   68
#define OFF_QC 0
#define OFF_QR 4352
#define OFF_RW 8704
#define OFF_PS 4352
#define OFF_KV 21760
#define ATTN_FLOATS 27200

__global__ void __launch_bounds__(128, 2)
attn_mma_kernel(const float* __restrict__ QC, const float* __restrict__ QR,
                const float* __restrict__ K,  const float* __restrict__ Vt,
                const float* __restrict__ RW, float* __restrict__ AO) {
    extern __shared__ float sm[];
    int tid = threadIdx.x;
    int wid = tid >> 5, lane = tid & 31;
    int lr = lane >> 2, lq = lane & 3;
    int wm = wid;
    int t0 = blockIdx.x * TQ, h = blockIdx.y, b = blockIdx.z;
    size_t bh = (size_t)(b * HEADS + h);
    const float* qcb = QC + (bh << 16) + (size_t)t0 * 64;
    const float* qrb = QR + (bh << 16) + (size_t)t0 * 64;
    const float* kb  = K  + (bh << 16);
    const float* vb  = Vt + (bh << 16);
    int j0base = t0 - WIN;
    int r = wm * 16 + lr;

    #pragma unroll
    for (int l = 0; l < 8; l++) {
        int fidx = tid + 128 * l;
        int t = fidx >> 4, d = (fidx & 15) << 2;
        *(float4*)&sm[OFF_QC + t * AQP + d] = *(const float4*)(qcb + t * 64 + d);
        *(float4*)&sm[OFF_QR + t * AQP + d] = *(const float4*)(qrb + t * 64 + d);
    }
    #pragma unroll 4
    for (int l = 0; l < 34; l++) {
        int fidx = tid + 128 * l;
        int u = fidx >> 4, d = (fidx & 15) << 2;
        *(float4*)&sm[OFF_RW + u * RWP + d] = *(const float4*)(RW + u * 64 + d);
    }
    __syncthreads();

    {
        float pc[34][4];
        #pragma unroll
        for (int nt = 0; nt < 34; nt++)
            #pragma unroll
            for (int e = 0; e < 4; e++) pc[nt][e] = 0.0f;
        #pragma unroll
        for (int k8 = 0; k8 < 8; k8++) {
            int kbi = k8 * 8 + 2 * lq;
            float2 alo = *(const float2*)&sm[OFF_QR + r * AQP + kbi];
            float2 ahi = *(const float2*)&sm[OFF_QR + (r + 8) * AQP + kbi];
            #pragma unroll
            for (int nt = 0; nt < 34; nt++) {
                int cc = nt * 8 + lr;
                float2 bv = *(const float2*)&sm[OFF_RW + cc * RWP + kbi];
                mma8(pc[nt], alo, ahi, bv.x, bv.y);
            }
        }
        __syncthreads();
        int m = wm * 16 + lr;
        #pragma unroll
        for (int nt = 0; nt < 34; nt++) {
            int cl = nt * 8 + 2 * lq;
            *(float2*)&sm[OFF_PS + m * PPW + cl]       = make_float2(pc[nt][0], pc[nt][1]);
            *(float2*)&sm[OFF_PS + (m + 8) * PPW + cl] = make_float2(pc[nt][2], pc[nt][3]);
        }
    }

    float sc[40][4];
    #pragma unroll
    for (int c = 0; c < 5; c++) {
        int j0 = j0base + c * 64;
        bool live = (j0 > -64) && (j0 < SEQ);
        __syncthreads();
        if (live) {
            #pragma unroll
            for (int l = 0; l < 8; l++) {
                int fidx = tid + 128 * l;
                int jl = fidx >> 4, d = (fidx & 15) << 2;
                int jg = j0 + jl;
                float4 v = make_float4(0.f, 0.f, 0.f, 0.f);
                if (jg >= 0 && jg < SEQ) v = *(const float4*)(kb + (size_t)jg * 64 + d);
                *(float4*)&sm[OFF_KV + jl * KVP + d] = v;
            }
        }
        __syncthreads();

        if (live) {
            #pragma unroll
            for (int nt = 0; nt < 8; nt++)
                #pragma unroll
                for (int e = 0; e < 4; e++) sc[c * 8 + nt][e] = 0.0f;
            #pragma unroll
            for (int k8 = 0; k8 < 8; k8++) {
                int kbi = k8 * 8 + 2 * lq;
                float2 alo = *(const float2*)&sm[OFF_QC + r * AQP + kbi];
                float2 ahi = *(const float2*)&sm[OFF_QC + (r + 8) * AQP + kbi];
                #pragma unroll
                for (int nt = 0; nt < 8; nt++) {
                    int cc = nt * 8 + lr;
                    float2 bv = *(const float2*)&sm[OFF_KV + cc * KVP + kbi];
                    mma8(sc[c * 8 + nt], alo, ahi, bv.x, bv.y);
                }
            }
            #pragma unroll
            for (int nt = 0; nt < 8; nt++) {
                int cl = nt * 8 + 2 * lq;
                #pragma unroll
                for (int e = 0; e < 4; e++) {
                    int m  = wm * 16 + lr + (e >> 1) * 8;
                    int jl = c * 64 + cl + (e & 1);
                    int jg = j0base + jl;
                    int u  = m - jl + 256;
                    float val = -1e30f;
                    if (jg >= 0 && jg < SEQ && u >= 0 && u < NREL)
                        val = (sc[c * 8 + nt][e] + sm[OFF_PS + m * PPW + u]) * SCALE;
                    sc[c * 8 + nt][e] = val;
                }
            }
        } else {
            #pragma unroll
            for (int nt = 0; nt < 8; nt++)
                #pragma unroll
                for (int e = 0; e < 4; e++) sc[c * 8 + nt][e] = -1e30f;
        }
    }

    {
        float mx0 = -1e30f, mx1 = -1e30f;
        #pragma unroll
        for (int nt = 0; nt < 40; nt++) {
            mx0 = fmaxf(mx0, fmaxf(sc[nt][0], sc[nt][1]));
            mx1 = fmaxf(mx1, fmaxf(sc[nt][2], sc[nt][3]));
        }
        #pragma unroll
        for (int o = 1; o < 4; o <<= 1) {
            mx0 = fmaxf(mx0, __shfl_xor_sync(0xffffffffu, mx0, o));
            mx1 = fmaxf(mx1, __shfl_xor_sync(0xffffffffu, mx1, o));
        }
        float s0 = 0.0f, s1 = 0.0f;
        #pragma unroll
        for (int nt = 0; nt < 40; nt++) {
            sc[nt][0] = __expf(sc[nt][0] - mx0);
            sc[nt][1] = __expf(sc[nt][1] - mx0);
            sc[nt][2] = __expf(sc[nt][2] - mx1);
            sc[nt][3] = __expf(sc[nt][3] - mx1);
            s0 += sc[nt][0] + sc[nt][1];
            s1 += sc[nt][2] + sc[nt][3];
        }
        #pragma unroll
        for (int o = 1; o < 4; o <<= 1) {
            s0 += __shfl_xor_sync(0xffffffffu, s0, o);
            s1 += __shfl_xor_sync(0xffffffffu, s1, o);
        }
        float i0 = 1.0f / s0, i1 = 1.0f / s1;
        #pragma unroll
        for (int nt = 0; nt < 40; nt++) {
            sc[nt][0] = to_tf32(sc[nt][0] * i0);
            sc[nt][1] = to_tf32(sc[nt][1] * i0);
            sc[nt][2] = to_tf32(sc[nt][2] * i1);
            sc[nt][3] = to_tf32(sc[nt][3] * i1);
        }
    }

    float ao_[8][4];
    #pragma unroll
    for (int nt = 0; nt < 8; nt++)
        #pragma unroll
        for (int e = 0; e < 4; e++) ao_[nt][e] = 0.0f;

    #pragma unroll
    for (int c = 0; c < 5; c++) {
        int j0 = j0base + c * 64;
        bool live = (j0 > -64) && (j0 < SEQ);
        __syncthreads();
        if (live) {
            #pragma unroll
            for (int l = 0; l < 8; l++) {
                int fidx = tid + 128 * l;
                int dd = fidx >> 4, jl4 = (fidx & 15) << 2;
                int jg = j0 + jl4;
                float4 v;
                if (j0 >= 0 && j0 + 63 < SEQ) {
                    v = *(const float4*)(vb + (size_t)dd * 1024 + jg);
                } else {
                    v.x = (jg     >= 0 && jg     < SEQ) ? vb[(size_t)dd * 1024 + jg]     : 0.f;
                    v.y = (jg + 1 >= 0 && jg + 1 < SEQ) ? vb[(size_t)dd * 1024 + jg + 1] : 0.f;
                    v.z = (jg + 2 >= 0 && jg + 2 < SEQ) ? vb[(size_t)dd * 1024 + jg + 2] : 0.f;
                    v.w = (jg + 3 >= 0 && jg + 3 < SEQ) ? vb[(size_t)dd * 1024 + jg + 3] : 0.f;
                }
                *(float4*)&sm[OFF_KV + dd * KVP + jl4] = v;
            }
        }
        __syncthreads();

        if (live) {
            #pragma unroll
            for (int kk = 0; kk < 8; kk++) {
                int kbi = kk * 8 + 2 * lq;
                float2 alo = make_float2(sc[c * 8 + kk][0], sc[c * 8 + kk][1]);
                float2 ahi = make_float2(sc[c * 8 + kk][2], sc[c * 8 + kk][3]);
                #pragma unroll
                for (int nt = 0; nt < 8; nt++) {
                    int cc = nt * 8 + lr;
                    float2 bv = *(const float2*)&sm[OFF_KV + cc * KVP + kbi];
                    mma8(ao_[nt], alo, ahi, bv.x, bv.y);
                }
            }
        }
    }

    // AO stored tf32-rounded (feeds proj GEMM A via cp.async, no cvt there)
    #pragma unroll
    for (int nt = 0; nt < 8; nt++) {
        int n = nt * 8 + 2 * lq;
        int m = wm * 16 + lr;
        size_t o0 = ((size_t)(b * SEQ + t0 + m)) * HID + h * 64 + n;
        size_t o1 = ((size_t)(b * SEQ + t0 + m + 8)) * HID + h * 64 + n;
        *(float2*)&AO[o0] = make_float2(to_tf32(ao_[nt][0]), to_tf32(ao_[nt][1]));
        *(float2*)&AO[o1] = make_float2(to_tf32(ao_[nt][2]), to_tf32(ao_[nt][3]));
    }
}

// ---------------- host ----------------
extern "C" void kernel_launch(void* const* d_in, const int* in_sizes, int n_in,
                              void* d_out, int out_size) {
    const float* x    = (const float*)d_in[0];
    const float* Wq   = (const float*)d_in[1];
    const float* Wk   = (const float*)d_in[2];
    const float* Wv   = (const float*)d_in[3];
    const float* cb   = (const float*)d_in[4];
    const float* rb   = (const float*)d_in[5];
    const float* Wrel = (const float*)d_in[6];
    const float* brel = (const float*)d_in[7];
    const float* Wo   = (const float*)d_in[8];
    const float* bo   = (const float*)d_in[9];
    float* out = (float*)d_out;

    float *qc, *qr, *kt, *vt, *ao, *rwin;
    float *xr, *wq, *wk, *wv, *wo;
    cudaGetSymbolAddress((void**)&qc,   g_qc);
    cudaGetSymbolAddress((void**)&qr,   g_qr);
    cudaGetSymbolAddress((void**)&kt,   g_k);
    cudaGetSymbolAddress((void**)&vt,   g_v);
    cudaGetSymbolAddress((void**)&ao,   g_ao);
    cudaGetSymbolAddress((void**)&rwin, g_rwin);
    cudaGetSymbolAddress((void**)&xr,   g_xr);
    cudaGetSymbolAddress((void**)&wq,   g_wq);
    cudaGetSymbolAddress((void**)&wk,   g_wk);
    cudaGetSymbolAddress((void**)&wv,   g_wv);
    cudaGetSymbolAddress((void**)&wo,   g_wo);

    int total4 = XN4 + 4 * WN4;
    prep_round<<<(total4 + 255) / 256, 256>>>(x, Wq, Wk, Wv, Wo, xr, wq, wk, wv, wo);
    rwin_kernel<<<(NRELP * 64 + 255) / 256, 256>>>(Wrel, brel, rwin);

    gemm_qkv_tf32<<<dim3(24, 32), 128>>>(xr, wq, wk, wv, cb, rb, qc, qr, kt, vt);

    size_t attn_smem = (size_t)ATTN_FLOATS * sizeof(float);
    cudaFuncSetAttribute(attn_mma_kernel, cudaFuncAttributeMaxDynamicSharedMemorySize,
                         (int)attn_smem);
    attn_mma_kernel<<<dim3(SEQ / TQ, HEADS, BATCH), 128, attn_smem>>>(
        qc, qr, kt, vt, rwin, ao);

    gemm_proj_tf32<<<dim3(8, 32), 128>>>(ao, wo, bo, out);
}